// round 13
// baseline (speedup 1.0000x reference)
#include <cuda_runtime.h>
#include <cstdint>
#include <math.h>

// ---------------- device scratch (no allocations allowed) ----------------
__device__ float g_h1[32*64*64*64];     // conv1 output (33.5 MB)
__device__ float g_h2[32*64*64*64];     // conv2 output (33.5 MB)
__device__ float g_logits64[32*64*64];  // conv3 output (low-res logits)
__device__ float g_vmax[32*256*256];    // vertical 9-max temp (8 MB)
__device__ float g_w1r[256*9*64];       // W1 reformatted [(ic*9+tap)][oc]
__device__ float g_w2r[64*9*64];        // W2 reformatted
__device__ int   g_pos_idx[32*3];
__device__ int   g_pos_valid[32*3];
__device__ int   g_neg_idx[32*2];
__device__ int   g_neg_valid[32*2];

#define PQ 8   // partial blocks per batch for peak/neg reductions
__device__ float g_ppv[32*PQ*4];  // [b][q][0..2]=top3 vals, [3]=argmax val
__device__ int   g_ppi[32*PQ*4];
__device__ float g_npv[32*PQ*2];
__device__ int   g_npi[32*PQ*2];

// ---------------- packed f32x2 helpers (sm_100+) ----------------
typedef unsigned long long ull;
struct __align__(16) ULL2 { ull x, y; };

__device__ __forceinline__ ull pk2(float lo, float hi)
{
    ull r;
    asm("mov.b64 %0, {%1, %2};" : "=l"(r) : "f"(lo), "f"(hi));
    return r;
}
__device__ __forceinline__ void upk2(ull v, float& lo, float& hi)
{
    asm("mov.b64 {%0, %1}, %2;" : "=f"(lo), "=f"(hi) : "l"(v));
}
__device__ __forceinline__ void fma2(ull& d, ull a, ull b)
{
    asm("fma.rn.f32x2 %0, %1, %2, %0;" : "+l"(d) : "l"(a), "l"(b));
}

// ---------------- cp.async helpers ----------------
__device__ __forceinline__ void cp4_zfill(uint32_t smem_dst, const void* gsrc, int src_sz)
{
    asm volatile("cp.async.ca.shared.global [%0], [%1], 4, %2;"
                 :: "r"(smem_dst), "l"(gsrc), "r"(src_sz));
}
__device__ __forceinline__ void cp16(uint32_t smem_dst, const void* gsrc)
{
    asm volatile("cp.async.cg.shared.global [%0], [%1], 16;"
                 :: "r"(smem_dst), "l"(gsrc));
}
__device__ __forceinline__ void cp_commit()
{
    asm volatile("cp.async.commit_group;");
}
template<int N>
__device__ __forceinline__ void cp_wait()
{
    asm volatile("cp.async.wait_group %0;" :: "n"(N));
}

// ---------------- weight reformat: W[oc][ic][3][3] -> wr[(ic*9+tap)][oc] ----
__global__ void k_reformat(const float* __restrict__ W, float* __restrict__ out, int cin)
{
    int i = blockIdx.x * blockDim.x + threadIdx.x;
    int total = 64 * cin * 9;
    if (i >= total) return;
    int oc  = i & 63;
    int rest = i >> 6;       // ic*9 + tap
    int tap = rest % 9;
    int ic  = rest / 9;
    out[i] = W[(oc * cin + ic) * 9 + tap];
}

// ---------------- 3x3 conv + BN + ReLU (SAME), 64x64 spatial, 64 out ch ----
// Round-9 winner + padded input rows: the staged halo tile uses a 20-float
// row stride (18 data + 2 pad), so each thread's 10-input row segment is
// 16B-aligned (seg in {0,8}) and loads as 3 LDS.128 instead of 10 LDS.32.
// cp.async double-buffered staging (stage-then-wait<1> overlap), icl
// unrolled x2, fma.rn.f32x2 accumulators. Bit-identical math order.
template<int CIN>
__global__ __launch_bounds__(256, 2)
void k_conv3x3(const float* __restrict__ in, float* __restrict__ out,
               const float* __restrict__ wr,
               const float* __restrict__ gg, const float* __restrict__ bb,
               const float* __restrict__ mm, const float* __restrict__ vv)
{
    __shared__ __align__(16) float s_in[2][8 * 360];   // 2 x (8 ch x 18 rows x 20 floats)
    __shared__ __align__(16) float s_w [2][8 * 9 * 64];// 2 x (8 ch x 9 taps x 64 oc)

    const int b    = blockIdx.y;
    const int tile = blockIdx.x;
    const int ty0  = (tile >> 2) * 16;
    const int tx0  = (tile & 3) * 16;
    const int tid  = threadIdx.x;
    const int t_oc = tid >> 5;           // 0..7 (uniform within warp -> broadcast)
    const int t_px = tid & 31;           // 0..31
    const int row  = t_px >> 1;          // 0..15 output row within tile
    const int seg  = (t_px & 1) * 8;     // 0 or 8: x-segment start

    const uint32_t s_in_base = (uint32_t)__cvta_generic_to_shared(&s_in[0][0]);
    const uint32_t s_w_base  = (uint32_t)__cvta_generic_to_shared(&s_w[0][0]);

    // ---- async stage of one 8-channel chunk into buffer d ----
    auto stage = [&](int c0, int d) {
        uint32_t in_dst = s_in_base + d * (8 * 360 * 4);
        uint32_t w_dst  = s_w_base  + d * (8 * 9 * 64 * 4);
        // input halo: per-element 4B cp.async with zfill; rows padded 18->20
        #pragma unroll
        for (int k = 0; k < 12; ++k) {
            int i = tid + k * 256;
            if (i < 8 * 360) {
                int icl = i / 360;
                int rem = i - icl * 360;
                int yy  = rem / 20;
                int xx  = rem - yy * 20;
                if (xx < 18) {
                    int gy = ty0 - 1 + yy, gx = tx0 - 1 + xx;
                    bool ok = ((unsigned)gy < 64u) & ((unsigned)gx < 64u);
                    const float* src = ok ? &in[((b * CIN + c0 + icl) * 64 + gy) * 64 + gx]
                                          : in;   // dummy valid address when zfilled
                    cp4_zfill(in_dst + i * 4, src, ok ? 4 : 0);
                }
            }
        }
        // weights: contiguous, 16B vectors (4608 floats = 1152 x 16B)
        #pragma unroll
        for (int k = 0; k < 5; ++k) {
            int i = tid + k * 256;                    // vec4 index
            if (i < 1152)
                cp16(w_dst + i * 16, &wr[c0 * 576 + i * 4]);
        }
        cp_commit();
    };

    ull acc[8][4];                       // 8 px x 4 oc-pairs (oc 2k, 2k+1)
    #pragma unroll
    for (int j = 0; j < 8; ++j)
        #pragma unroll
        for (int k = 0; k < 4; ++k) acc[j][k] = 0ull;

    const int nchunk = CIN / 8;
    stage(0, 0);                         // preload chunk 0

    for (int c = 0; c < nchunk; ++c) {
        const int d = c & 1;
        if (c + 1 < nchunk) {
            stage((c + 1) * 8, d ^ 1);   // overlap: next chunk in flight
            cp_wait<1>();                // chunk c's group complete
        } else {
            cp_wait<0>();
        }
        __syncthreads();                 // staged data visible to all

        #pragma unroll 2
        for (int icl = 0; icl < 8; ++icl) {
            const float* si = &s_in[d][icl * 360 + row * 20 + seg];
            const float* sw = &s_w[d][icl * 576 + t_oc * 8];
            #pragma unroll
            for (int ty = 0; ty < 3; ++ty) {
                // 3x LDS.128 cover the 10 inputs of this row (aligned via pad)
                const float4 q0 = *(const float4*)(si + ty * 20);
                const float4 q1 = *(const float4*)(si + ty * 20 + 4);
                const float4 q2 = *(const float4*)(si + ty * 20 + 8);
                ull rin2[10];
                rin2[0] = pk2(q0.x, q0.x);
                rin2[1] = pk2(q0.y, q0.y);
                rin2[2] = pk2(q0.z, q0.z);
                rin2[3] = pk2(q0.w, q0.w);
                rin2[4] = pk2(q1.x, q1.x);
                rin2[5] = pk2(q1.y, q1.y);
                rin2[6] = pk2(q1.z, q1.z);
                rin2[7] = pk2(q1.w, q1.w);
                rin2[8] = pk2(q2.x, q2.x);
                rin2[9] = pk2(q2.y, q2.y);
                #pragma unroll
                for (int tx = 0; tx < 3; ++tx) {
                    const int tap = ty * 3 + tx;
                    const ULL2 wA = *(const ULL2*)&sw[tap * 64];      // oc 0-3
                    const ULL2 wB = *(const ULL2*)&sw[tap * 64 + 4];  // oc 4-7
                    #pragma unroll
                    for (int j = 0; j < 8; ++j) {
                        ull xp = rin2[j + tx];
                        fma2(acc[j][0], xp, wA.x);
                        fma2(acc[j][1], xp, wA.y);
                        fma2(acc[j][2], xp, wB.x);
                        fma2(acc[j][3], xp, wB.y);
                    }
                }
            }
        }
        __syncthreads();                 // compute done before buffer d is restaged
    }

    // epilogue: BN (scale/shift) + ReLU, vectorized stores
    const int y = ty0 + row, x = tx0 + seg;
    #pragma unroll
    for (int kp = 0; kp < 4; ++kp) {
        int oc0 = t_oc * 8 + 2 * kp;
        int oc1 = oc0 + 1;
        float sc0 = gg[oc0] / sqrtf(vv[oc0] + 1e-5f);
        float sh0 = bb[oc0] - mm[oc0] * sc0;
        float sc1 = gg[oc1] / sqrtf(vv[oc1] + 1e-5f);
        float sh1 = bb[oc1] - mm[oc1] * sc1;
        float a0[8], a1[8];
        #pragma unroll
        for (int j = 0; j < 8; ++j) upk2(acc[j][kp], a0[j], a1[j]);

        float4 o0, o1;
        o0.x = fmaxf(fmaf(a0[0], sc0, sh0), 0.f);
        o0.y = fmaxf(fmaf(a0[1], sc0, sh0), 0.f);
        o0.z = fmaxf(fmaf(a0[2], sc0, sh0), 0.f);
        o0.w = fmaxf(fmaf(a0[3], sc0, sh0), 0.f);
        o1.x = fmaxf(fmaf(a0[4], sc0, sh0), 0.f);
        o1.y = fmaxf(fmaf(a0[5], sc0, sh0), 0.f);
        o1.z = fmaxf(fmaf(a0[6], sc0, sh0), 0.f);
        o1.w = fmaxf(fmaf(a0[7], sc0, sh0), 0.f);
        float* dst0 = &out[((b * 64 + oc0) * 64 + y) * 64 + x];
        *(float4*)dst0 = o0;
        *(float4*)(dst0 + 4) = o1;

        o0.x = fmaxf(fmaf(a1[0], sc1, sh1), 0.f);
        o0.y = fmaxf(fmaf(a1[1], sc1, sh1), 0.f);
        o0.z = fmaxf(fmaf(a1[2], sc1, sh1), 0.f);
        o0.w = fmaxf(fmaf(a1[3], sc1, sh1), 0.f);
        o1.x = fmaxf(fmaf(a1[4], sc1, sh1), 0.f);
        o1.y = fmaxf(fmaf(a1[5], sc1, sh1), 0.f);
        o1.z = fmaxf(fmaf(a1[6], sc1, sh1), 0.f);
        o1.w = fmaxf(fmaf(a1[7], sc1, sh1), 0.f);
        float* dst1 = &out[((b * 64 + oc1) * 64 + y) * 64 + x];
        *(float4*)dst1 = o0;
        *(float4*)(dst1 + 4) = o1;
    }
}

// ---------------- 1x1 conv (64 -> 1) + bias ----------------
__global__ void k_conv1x1(const float* __restrict__ in, const float* __restrict__ w3,
                          const float* __restrict__ b3, float* __restrict__ out)
{
    int i = blockIdx.x * blockDim.x + threadIdx.x;   // 131072 pixels
    int b = i >> 12;
    int p = i & 4095;
    const float* base = in + (size_t)(b * 64) * 4096 + p;
    float s = 0.f;
    #pragma unroll 8
    for (int ic = 0; ic < 64; ++ic)
        s = fmaf(base[(size_t)ic * 4096], __ldg(&w3[ic]), s);
    out[i] = s + b3[0];
}

// ---------------- bilinear resize 64->256 (jax.image.resize linear) + sigmoid
__global__ void k_resize(const float* __restrict__ lg,
                         float* __restrict__ heat, float* __restrict__ logits_out)
{
    int ox = threadIdx.x;       // 0..255
    int oy = blockIdx.x;        // 0..255
    int b  = blockIdx.y;        // 0..31

    float sy = 0.25f * oy - 0.375f;
    float sx = 0.25f * ox - 0.375f;
    int y0; float fy;
    if (sy <= 0.f)        { y0 = 0;  fy = 0.f; }
    else if (sy >= 63.f)  { y0 = 62; fy = 1.f; }
    else                  { y0 = (int)sy; fy = sy - (float)y0; }
    int x0; float fx;
    if (sx <= 0.f)        { x0 = 0;  fx = 0.f; }
    else if (sx >= 63.f)  { x0 = 62; fx = 1.f; }
    else                  { x0 = (int)sx; fx = sx - (float)x0; }

    const float* src = lg + b * 4096;
    float v00 = src[y0 * 64 + x0],     v01 = src[y0 * 64 + x0 + 1];
    float v10 = src[(y0+1) * 64 + x0], v11 = src[(y0+1) * 64 + x0 + 1];
    float a = v00 * (1.f - fx) + v01 * fx;
    float c = v10 * (1.f - fx) + v11 * fx;
    float val = a * (1.f - fy) + c * fy;

    int o = b * 65536 + oy * 256 + ox;
    logits_out[o] = val;
    heat[o] = 1.f / (1.f + expf(-val));
}

// ---------------- vertical 9-tap max ----------------
__global__ void k_vmax(const float* __restrict__ heat, float* __restrict__ vm)
{
    int b  = blockIdx.y;
    int i0 = blockIdx.x * blockDim.x + threadIdx.x;  // 0..65535
    int y = i0 >> 8, x = i0 & 255;
    const float* s = heat + b * 65536;
    float mv = -INFINITY;
    #pragma unroll
    for (int dy = -4; dy <= 4; ++dy) {
        int yy = y + dy;
        if ((unsigned)yy < 256u) mv = fmaxf(mv, s[yy * 256 + x]);
    }
    vm[b * 65536 + i0] = mv;
}

// ---------------- helpers for tie-broken top-k merge ----------------
__device__ __forceinline__ void ins3(float h, int p, float* bv, int* bi)
{
    if (h > bv[0] || (h == bv[0] && p < bi[0])) {
        bv[2]=bv[1]; bi[2]=bi[1]; bv[1]=bv[0]; bi[1]=bi[0]; bv[0]=h; bi[0]=p;
    } else if (h > bv[1] || (h == bv[1] && p < bi[1])) {
        bv[2]=bv[1]; bi[2]=bi[1]; bv[1]=h; bi[1]=p;
    } else if (h > bv[2] || (h == bv[2] && p < bi[2])) {
        bv[2]=h; bi[2]=p;
    }
}
__device__ __forceinline__ void ins2(float h, int p, float* bv, int* bi)
{
    if (h > bv[0] || (h == bv[0] && p < bi[0])) {
        bv[1]=bv[0]; bi[1]=bi[0]; bv[0]=h; bi[0]=p;
    } else if (h > bv[1] || (h == bv[1] && p < bi[1])) {
        bv[1]=h; bi[1]=p;
    }
}

// ---------------- peak partial: each block handles 8192 px of one batch ----
__global__ void k_peaks_part(const float* __restrict__ heat, const float* __restrict__ vm)
{
    int b = blockIdx.y, q = blockIdx.x;
    int tid = threadIdx.x;
    const float* s = heat + b * 65536;
    const float* v = vm   + b * 65536;
    const int pbase = q * 8192;

    float tv[3] = {-INFINITY, -INFINITY, -INFINITY};
    int   ti[3] = {0x7fffffff, 0x7fffffff, 0x7fffffff};
    float av = -INFINITY; int ai = 0x7fffffff;

    for (int p = pbase + tid; p < pbase + 8192; p += 256) {
        float h = s[p];
        if (h > av) { av = h; ai = p; }    // ascending p, strict > -> earliest
        int y = p >> 8, x = p & 255;
        float mx = -INFINITY;
        #pragma unroll
        for (int dx = -4; dx <= 4; ++dx) {
            int xx = x + dx;
            if ((unsigned)xx < 256u) mx = fmaxf(mx, v[y * 256 + xx]);
        }
        if (h == mx && h > 0.1f) {
            if (h > tv[0]) {
                tv[2]=tv[1]; ti[2]=ti[1]; tv[1]=tv[0]; ti[1]=ti[0]; tv[0]=h; ti[0]=p;
            } else if (h > tv[1]) {
                tv[2]=tv[1]; ti[2]=ti[1]; tv[1]=h; ti[1]=p;
            } else if (h > tv[2]) {
                tv[2]=h; ti[2]=p;
            }
        }
    }

    __shared__ float sv[256*3], sav[256];
    __shared__ int   sj[256*3], sai[256];
    __shared__ float wv[8*3], wav[8];
    __shared__ int   wj[8*3], wai[8];
    #pragma unroll
    for (int k = 0; k < 3; ++k) { sv[tid*3+k] = tv[k]; sj[tid*3+k] = ti[k]; }
    sav[tid] = av; sai[tid] = ai;
    __syncthreads();

    if ((tid & 31) == 0) {
        int w = tid >> 5;
        float bv[3] = {-INFINITY,-INFINITY,-INFINITY};
        int   bi[3] = {0x7fffffff,0x7fffffff,0x7fffffff};
        float bav = -INFINITY; int bai = 0x7fffffff;
        for (int t = tid; t < tid + 32; ++t) {
            #pragma unroll
            for (int k = 0; k < 3; ++k) {
                float h = sv[t*3+k];
                if (h != -INFINITY) ins3(h, sj[t*3+k], bv, bi);
            }
            if (sav[t] > bav || (sav[t] == bav && sai[t] < bai)) { bav = sav[t]; bai = sai[t]; }
        }
        #pragma unroll
        for (int k = 0; k < 3; ++k) { wv[w*3+k] = bv[k]; wj[w*3+k] = bi[k]; }
        wav[w] = bav; wai[w] = bai;
    }
    __syncthreads();

    if (tid == 0) {
        float bv[3] = {-INFINITY,-INFINITY,-INFINITY};
        int   bi[3] = {0x7fffffff,0x7fffffff,0x7fffffff};
        float bav = -INFINITY; int bai = 0x7fffffff;
        for (int w = 0; w < 8; ++w) {
            #pragma unroll
            for (int k = 0; k < 3; ++k) {
                float h = wv[w*3+k];
                if (h != -INFINITY) ins3(h, wj[w*3+k], bv, bi);
            }
            if (wav[w] > bav || (wav[w] == bav && wai[w] < bai)) { bav = wav[w]; bai = wai[w]; }
        }
        int o = (b * PQ + q) * 4;
        #pragma unroll
        for (int k = 0; k < 3; ++k) { g_ppv[o+k] = bv[k]; g_ppi[o+k] = bi[k]; }
        g_ppv[o+3] = bav; g_ppi[o+3] = bai;
    }
}

// ---------------- merge peak partials -> g_pos ----------------
__global__ void k_pmerge()
{
    int b = threadIdx.x;
    if (b >= 32) return;
    float bv[3] = {-INFINITY,-INFINITY,-INFINITY};
    int   bi[3] = {0x7fffffff,0x7fffffff,0x7fffffff};
    float bav = -INFINITY; int bai = 0x7fffffff;
    for (int q = 0; q < PQ; ++q) {
        int o = (b * PQ + q) * 4;
        #pragma unroll
        for (int k = 0; k < 3; ++k) {
            float h = g_ppv[o+k];
            if (h != -INFINITY) ins3(h, g_ppi[o+k], bv, bi);
        }
        float avv = g_ppv[o+3]; int aii = g_ppi[o+3];
        if (avv > bav || (avv == bav && aii < bai)) { bav = avv; bai = aii; }
    }
    g_pos_idx[b*3+0]   = (bv[0] != -INFINITY) ? bi[0] : bai;
    g_pos_valid[b*3+0] = 1;
    g_pos_idx[b*3+1]   = bi[1];
    g_pos_valid[b*3+1] = (bv[1] != -INFINITY) ? 1 : 0;
    g_pos_idx[b*3+2]   = bi[2];
    g_pos_valid[b*3+2] = (bv[2] != -INFINITY) ? 1 : 0;
}

// ---------------- threefry2x32, key = (0, 42), 20 rounds --------------------
__device__ __forceinline__ void threefry2x32_dev(unsigned c0, unsigned c1,
                                                 unsigned &o0, unsigned &o1)
{
    const unsigned ks0 = 0u, ks1 = 42u, ks2 = 0x1BD11BDAu ^ 0u ^ 42u;
    unsigned x0 = c0 + ks0, x1 = c1 + ks1;
#define TFR(d) { x0 += x1; x1 = (x1 << d) | (x1 >> (32 - d)); x1 ^= x0; }
    TFR(13) TFR(15) TFR(26) TFR(6)  x0 += ks1; x1 += ks2 + 1u;
    TFR(17) TFR(29) TFR(16) TFR(24) x0 += ks2; x1 += ks0 + 2u;
    TFR(13) TFR(15) TFR(26) TFR(6)  x0 += ks0; x1 += ks1 + 3u;
    TFR(17) TFR(29) TFR(16) TFR(24) x0 += ks1; x1 += ks2 + 4u;
    TFR(13) TFR(15) TFR(26) TFR(6)  x0 += ks2; x1 += ks0 + 5u;
#undef TFR
    o0 = x0; o1 = x1;
}

// ---------------- negative partial: top-2 threefry uniforms over heat<0.3 ---
// (partitionable threefry: counter = (0, flat_index), bits = o0 ^ o1)
__global__ void k_neg_part(const float* __restrict__ heat)
{
    int b = blockIdx.y, q = blockIdx.x;
    int tid = threadIdx.x;
    const float* s = heat + b * 65536;
    const int pbase = q * 8192;

    int p0 = g_pos_valid[b*3+0] ? g_pos_idx[b*3+0] : -1;
    int p1 = g_pos_valid[b*3+1] ? g_pos_idx[b*3+1] : -1;
    int p2 = g_pos_valid[b*3+2] ? g_pos_idx[b*3+2] : -1;

    float tv[2] = {-INFINITY, -INFINITY};
    int   ti[2] = {0x7fffffff, 0x7fffffff};

    for (int p = pbase + tid; p < pbase + 8192; p += 256) {
        float h = s[p];
        if (h < 0.3f && p != p0 && p != p1 && p != p2) {
            unsigned n = (unsigned)(b * 65536 + p);
            unsigned w0, w1;
            threefry2x32_dev(0u, n, w0, w1);
            unsigned bits = w0 ^ w1;
            float r = __uint_as_float((bits >> 9) | 0x3f800000u) - 1.0f;
            if (r > tv[0]) { tv[1]=tv[0]; ti[1]=ti[0]; tv[0]=r; ti[0]=p; }
            else if (r > tv[1]) { tv[1]=r; ti[1]=p; }
        }
    }

    __shared__ float sv[256*2];
    __shared__ int   sj[256*2];
    __shared__ float wv[8*2];
    __shared__ int   wj[8*2];
    sv[tid*2+0] = tv[0]; sj[tid*2+0] = ti[0];
    sv[tid*2+1] = tv[1]; sj[tid*2+1] = ti[1];
    __syncthreads();

    if ((tid & 31) == 0) {
        int w = tid >> 5;
        float bv[2] = {-INFINITY,-INFINITY};
        int   bi[2] = {0x7fffffff,0x7fffffff};
        for (int t = tid; t < tid + 32; ++t) {
            #pragma unroll
            for (int k = 0; k < 2; ++k) {
                float r = sv[t*2+k];
                if (r != -INFINITY) ins2(r, sj[t*2+k], bv, bi);
            }
        }
        wv[w*2+0] = bv[0]; wj[w*2+0] = bi[0];
        wv[w*2+1] = bv[1]; wj[w*2+1] = bi[1];
    }
    __syncthreads();

    if (tid == 0) {
        float bv[2] = {-INFINITY,-INFINITY};
        int   bi[2] = {0x7fffffff,0x7fffffff};
        for (int w = 0; w < 8; ++w) {
            #pragma unroll
            for (int k = 0; k < 2; ++k) {
                float r = wv[w*2+k];
                if (r != -INFINITY) ins2(r, wj[w*2+k], bv, bi);
            }
        }
        int o = (b * PQ + q) * 2;
        g_npv[o+0] = bv[0]; g_npi[o+0] = bi[0];
        g_npv[o+1] = bv[1]; g_npi[o+1] = bi[1];
    }
}

// ---------------- merge negative partials -> g_neg ----------------
__global__ void k_nmerge()
{
    int b = threadIdx.x;
    if (b >= 32) return;
    float bv[2] = {-INFINITY,-INFINITY};
    int   bi[2] = {0x7fffffff,0x7fffffff};
    for (int q = 0; q < PQ; ++q) {
        int o = (b * PQ + q) * 2;
        #pragma unroll
        for (int k = 0; k < 2; ++k) {
            float r = g_npv[o+k];
            if (r != -INFINITY) ins2(r, g_npi[o+k], bv, bi);
        }
    }
    g_neg_idx[b*2+0]   = bi[0];
    g_neg_valid[b*2+0] = (bv[0] != -INFINITY) ? 1 : 0;
    g_neg_idx[b*2+1]   = bi[1];
    g_neg_valid[b*2+1] = (bv[1] != -INFINITY) ? 1 : 0;
}

// ---------------- assemble coords/labels (valid compacted first) -----------
__global__ void k_finalize(float* __restrict__ coords, float* __restrict__ labels)
{
    int b = threadIdx.x;
    if (b >= 32) return;
    int idxs[5], valid[5]; float lab[5];
    #pragma unroll
    for (int k = 0; k < 3; ++k) {
        idxs[k] = g_pos_idx[b*3+k]; valid[k] = g_pos_valid[b*3+k]; lab[k] = 1.f;
    }
    #pragma unroll
    for (int k = 0; k < 2; ++k) {
        idxs[3+k] = g_neg_idx[b*2+k]; valid[3+k] = g_neg_valid[b*2+k]; lab[3+k] = 0.f;
    }
    float cx[5], cy[5], cl[5];
    #pragma unroll
    for (int s = 0; s < 5; ++s) { cx[s] = 0.f; cy[s] = 0.f; cl[s] = -1.f; }
    int cnt = 0;
    for (int k = 0; k < 5; ++k) {
        if (valid[k]) {
            cx[cnt] = (float)(idxs[k] & 255);
            cy[cnt] = (float)(idxs[k] >> 8);
            cl[cnt] = lab[k];
            ++cnt;
        }
    }
    for (int s = 0; s < 5; ++s) {
        coords[b*10 + s*2 + 0] = cx[s];
        coords[b*10 + s*2 + 1] = cy[s];
        labels[b*5 + s] = cl[s];
    }
}

// ---------------- launch ----------------------------------------------------
extern "C" void kernel_launch(void* const* d_in, const int* in_sizes, int n_in,
                              void* d_out, int out_size)
{
    const float* x  = (const float*)d_in[0];
    const float* W1 = (const float*)d_in[1];
    const float* g1 = (const float*)d_in[2];
    const float* b1 = (const float*)d_in[3];
    const float* m1 = (const float*)d_in[4];
    const float* v1 = (const float*)d_in[5];
    const float* W2 = (const float*)d_in[6];
    const float* g2 = (const float*)d_in[7];
    const float* b2 = (const float*)d_in[8];
    const float* m2 = (const float*)d_in[9];
    const float* v2 = (const float*)d_in[10];
    const float* W3 = (const float*)d_in[11];
    const float* b3 = (const float*)d_in[12];

    float* out    = (float*)d_out;
    float* heat   = out;                 // 32*1*256*256 = 2097152
    float* coords = out + 2097152;       // 32*1*5*2     = 320
    float* labels = out + 2097472;       // 32*1*5       = 160
    float* logits = out + 2097632;       // 32*1*256*256 = 2097152

    float *p_h1, *p_h2, *p_l64, *p_vm, *p_w1r, *p_w2r;
    cudaGetSymbolAddress((void**)&p_h1,  g_h1);
    cudaGetSymbolAddress((void**)&p_h2,  g_h2);
    cudaGetSymbolAddress((void**)&p_l64, g_logits64);
    cudaGetSymbolAddress((void**)&p_vm,  g_vmax);
    cudaGetSymbolAddress((void**)&p_w1r, g_w1r);
    cudaGetSymbolAddress((void**)&p_w2r, g_w2r);

    k_reformat<<<576, 256>>>(W1, p_w1r, 256);
    k_reformat<<<144, 256>>>(W2, p_w2r, 64);

    k_conv3x3<256><<<dim3(16, 32), 256>>>(x,    p_h1, p_w1r, g1, b1, m1, v1);
    k_conv3x3<64> <<<dim3(16, 32), 256>>>(p_h1, p_h2, p_w2r, g2, b2, m2, v2);

    k_conv1x1<<<512, 256>>>(p_h2, W3, b3, p_l64);
    k_resize<<<dim3(256, 32), 256>>>(p_l64, heat, logits);

    k_vmax      <<<dim3(256, 32), 256>>>(heat, p_vm);
    k_peaks_part<<<dim3(PQ, 32), 256>>>(heat, p_vm);
    k_pmerge    <<<1, 32>>>();
    k_neg_part  <<<dim3(PQ, 32), 256>>>(heat);
    k_nmerge    <<<1, 32>>>();
    k_finalize  <<<1, 32>>>(coords, labels);
}

// round 15
// speedup vs baseline: 1.1064x; 1.1064x over previous
#include <cuda_runtime.h>
#include <cstdint>
#include <math.h>

typedef unsigned long long ull;
struct __align__(16) ULL2 { ull x, y; };

__device__ float g_h1[32*64*64*64];
__device__ float g_h2[32*64*64*64];
__device__ float g_logits64[32*64*64];
__device__ float g_vmax[32*256*256];
__device__ float g_w1r[256*9*64];
__device__ float g_w2r[64*9*64];
__device__ int   g_pos_idx[32*3], g_pos_valid[32*3], g_neg_idx[32*2], g_neg_valid[32*2];
#define PQ 8
__device__ float g_ppv[32*PQ*4]; __device__ int g_ppi[32*PQ*4];
__device__ float g_npv[32*PQ*2]; __device__ int g_npi[32*PQ*2];

__device__ __forceinline__ ull pk2(float lo, float hi)
{ ull r; asm("mov.b64 %0, {%1, %2};" : "=l"(r) : "f"(lo), "f"(hi)); return r; }
__device__ __forceinline__ void upk2(ull v, float& lo, float& hi)
{ asm("mov.b64 {%0, %1}, %2;" : "=f"(lo), "=f"(hi) : "l"(v)); }
__device__ __forceinline__ void fma2(ull& d, ull a, ull b)
{ asm("fma.rn.f32x2 %0, %1, %2, %0;" : "+l"(d) : "l"(a), "l"(b)); }

__device__ __forceinline__ void cp4_zfill(uint32_t d, const void* s, int sz)
{ asm volatile("cp.async.ca.shared.global [%0], [%1], 4, %2;" :: "r"(d), "l"(s), "r"(sz)); }
__device__ __forceinline__ void cp16(uint32_t d, const void* s)
{ asm volatile("cp.async.cg.shared.global [%0], [%1], 16;" :: "r"(d), "l"(s)); }
__device__ __forceinline__ void cp_commit() { asm volatile("cp.async.commit_group;"); }
template<int N> __device__ __forceinline__ void cp_wait()
{ asm volatile("cp.async.wait_group %0;" :: "n"(N) : "memory"); }

__global__ void k_reformat(const float* __restrict__ W, float* __restrict__ out, int cin)
{
    int i = blockIdx.x * blockDim.x + threadIdx.x;
    if (i >= 64 * cin * 9) return;
    int oc = i & 63, rest = i >> 6, tap = rest % 9, ic = rest / 9;
    out[i] = W[(oc * cin + ic) * 9 + tap];
}

// ---- 3x3 conv + BN + ReLU: round-9 compute, TRIPLE-buffered cp.async with
// ONE barrier per chunk: wait<1> -> sync -> stage(c+2) -> compute(c).
// The sync provides (a) visibility of chunk c's staged data (every warp's
// wait precedes it) and (b) completion of compute(c-1), which frees buffer
// (c+2)%3 == (c-1)%3 for restaging. Prefetch distance = 2 compute phases.
#define BUF_F 7200            // floats per buffer (2592 input + 4608 weights)
template<int CIN>
__global__ __launch_bounds__(256, 2)
void k_conv3x3(const float* __restrict__ in, float* __restrict__ out,
               const float* __restrict__ wr,
               const float* __restrict__ gg, const float* __restrict__ bb,
               const float* __restrict__ mm, const float* __restrict__ vv)
{
    extern __shared__ float dsm[];      // 3 * BUF_F floats

    const int b    = blockIdx.y;
    const int tile = blockIdx.x;
    const int ty0  = (tile >> 2) * 16;
    const int tx0  = (tile & 3) * 16;
    const int tid  = threadIdx.x;
    const int t_oc = tid >> 5;
    const int t_px = tid & 31;
    const int row  = t_px >> 1;
    const int seg  = (t_px & 1) * 8;

    const uint32_t sb = (uint32_t)__cvta_generic_to_shared(dsm);

    auto stage = [&](int c0, int d) {
        uint32_t in_dst = sb + d * (BUF_F * 4);
        uint32_t w_dst  = in_dst + 2592 * 4;
        #pragma unroll
        for (int k = 0; k < 11; ++k) {
            int i = tid + k * 256;
            if (i < 2592) {
                int icl = i / 324;
                int rem = i - icl * 324;
                int yy  = rem / 18;
                int xx  = rem - yy * 18;
                int gy = ty0 - 1 + yy, gx = tx0 - 1 + xx;
                bool ok = ((unsigned)gy < 64u) & ((unsigned)gx < 64u);
                const float* src = ok ? &in[((b * CIN + c0 + icl) * 64 + gy) * 64 + gx] : in;
                cp4_zfill(in_dst + i * 4, src, ok ? 4 : 0);
            }
        }
        #pragma unroll
        for (int k = 0; k < 5; ++k) {
            int i = tid + k * 256;
            if (i < 1152) cp16(w_dst + i * 16, &wr[c0 * 576 + i * 4]);
        }
        cp_commit();
    };

    ull acc[8][4];
    #pragma unroll
    for (int j = 0; j < 8; ++j)
        #pragma unroll
        for (int k = 0; k < 4; ++k) acc[j][k] = 0ull;

    const int nchunk = CIN / 8;
    stage(0, 0);
    if (nchunk > 1) stage(8, 1);

    int dc = 0;
    for (int c = 0; c < nchunk; ++c) {
        if (c + 1 < nchunk) cp_wait<1>(); else cp_wait<0>();
        __syncthreads();
        if (c + 2 < nchunk) {
            int ds = dc + 2; if (ds >= 3) ds -= 3;
            stage((c + 2) * 8, ds);
        }

        const float* s_in = dsm + dc * BUF_F;
        const float* s_w  = s_in + 2592;
        #pragma unroll 2
        for (int icl = 0; icl < 8; ++icl) {
            const float* si = &s_in[icl * 324 + row * 18 + seg];
            const float* sw = &s_w[icl * 576 + t_oc * 8];
            #pragma unroll
            for (int ty = 0; ty < 3; ++ty) {
                ull rin2[10];
                #pragma unroll
                for (int xx = 0; xx < 10; ++xx) {
                    float v = si[ty * 18 + xx];
                    rin2[xx] = pk2(v, v);
                }
                #pragma unroll
                for (int tx = 0; tx < 3; ++tx) {
                    const int tap = ty * 3 + tx;
                    const ULL2 wA = *(const ULL2*)&sw[tap * 64];
                    const ULL2 wB = *(const ULL2*)&sw[tap * 64 + 4];
                    #pragma unroll
                    for (int j = 0; j < 8; ++j) {
                        ull xp = rin2[j + tx];
                        fma2(acc[j][0], xp, wA.x);
                        fma2(acc[j][1], xp, wA.y);
                        fma2(acc[j][2], xp, wB.x);
                        fma2(acc[j][3], xp, wB.y);
                    }
                }
            }
        }
        if (++dc == 3) dc = 0;
    }

    const int y = ty0 + row, x = tx0 + seg;
    #pragma unroll
    for (int kp = 0; kp < 4; ++kp) {
        int oc0 = t_oc * 8 + 2 * kp, oc1 = oc0 + 1;
        float sc0 = gg[oc0] / sqrtf(vv[oc0] + 1e-5f);
        float sh0 = bb[oc0] - mm[oc0] * sc0;
        float sc1 = gg[oc1] / sqrtf(vv[oc1] + 1e-5f);
        float sh1 = bb[oc1] - mm[oc1] * sc1;
        float a0[8], a1[8];
        #pragma unroll
        for (int j = 0; j < 8; ++j) upk2(acc[j][kp], a0[j], a1[j]);

        float4 o0, o1;
        o0.x = fmaxf(fmaf(a0[0], sc0, sh0), 0.f);
        o0.y = fmaxf(fmaf(a0[1], sc0, sh0), 0.f);
        o0.z = fmaxf(fmaf(a0[2], sc0, sh0), 0.f);
        o0.w = fmaxf(fmaf(a0[3], sc0, sh0), 0.f);
        o1.x = fmaxf(fmaf(a0[4], sc0, sh0), 0.f);
        o1.y = fmaxf(fmaf(a0[5], sc0, sh0), 0.f);
        o1.z = fmaxf(fmaf(a0[6], sc0, sh0), 0.f);
        o1.w = fmaxf(fmaf(a0[7], sc0, sh0), 0.f);
        float* dst0 = &out[((b * 64 + oc0) * 64 + y) * 64 + x];
        *(float4*)dst0 = o0;
        *(float4*)(dst0 + 4) = o1;

        o0.x = fmaxf(fmaf(a1[0], sc1, sh1), 0.f);
        o0.y = fmaxf(fmaf(a1[1], sc1, sh1), 0.f);
        o0.z = fmaxf(fmaf(a1[2], sc1, sh1), 0.f);
        o0.w = fmaxf(fmaf(a1[3], sc1, sh1), 0.f);
        o1.x = fmaxf(fmaf(a1[4], sc1, sh1), 0.f);
        o1.y = fmaxf(fmaf(a1[5], sc1, sh1), 0.f);
        o1.z = fmaxf(fmaf(a1[6], sc1, sh1), 0.f);
        o1.w = fmaxf(fmaf(a1[7], sc1, sh1), 0.f);
        float* dst1 = &out[((b * 64 + oc1) * 64 + y) * 64 + x];
        *(float4*)dst1 = o0;
        *(float4*)(dst1 + 4) = o1;
    }
}

__global__ void k_conv1x1(const float* __restrict__ in, const float* __restrict__ w3,
                          const float* __restrict__ b3, float* __restrict__ out)
{
    int i = blockIdx.x * blockDim.x + threadIdx.x;
    int b = i >> 12, p = i & 4095;
    const float* base = in + (size_t)(b * 64) * 4096 + p;
    float s = 0.f;
    #pragma unroll 8
    for (int ic = 0; ic < 64; ++ic)
        s = fmaf(base[(size_t)ic * 4096], __ldg(&w3[ic]), s);
    out[i] = s + b3[0];
}

__global__ void k_resize(const float* __restrict__ lg,
                         float* __restrict__ heat, float* __restrict__ logits_out)
{
    int ox = threadIdx.x, oy = blockIdx.x, b = blockIdx.y;
    float sy = 0.25f * oy - 0.375f;
    float sx = 0.25f * ox - 0.375f;
    int y0; float fy;
    if (sy <= 0.f)       { y0 = 0;  fy = 0.f; }
    else if (sy >= 63.f) { y0 = 62; fy = 1.f; }
    else                 { y0 = (int)sy; fy = sy - (float)y0; }
    int x0; float fx;
    if (sx <= 0.f)       { x0 = 0;  fx = 0.f; }
    else if (sx >= 63.f) { x0 = 62; fx = 1.f; }
    else                 { x0 = (int)sx; fx = sx - (float)x0; }
    const float* src = lg + b * 4096;
    float v00 = src[y0 * 64 + x0],     v01 = src[y0 * 64 + x0 + 1];
    float v10 = src[(y0+1) * 64 + x0], v11 = src[(y0+1) * 64 + x0 + 1];
    float a = v00 * (1.f - fx) + v01 * fx;
    float c = v10 * (1.f - fx) + v11 * fx;
    float val = a * (1.f - fy) + c * fy;
    int o = b * 65536 + oy * 256 + ox;
    logits_out[o] = val;
    heat[o] = 1.f / (1.f + expf(-val));
}

__global__ void k_vmax(const float* __restrict__ heat, float* __restrict__ vm)
{
    int b = blockIdx.y, i0 = blockIdx.x * blockDim.x + threadIdx.x;
    int y = i0 >> 8, x = i0 & 255;
    const float* s = heat + b * 65536;
    float mv = -INFINITY;
    #pragma unroll
    for (int dy = -4; dy <= 4; ++dy) {
        int yy = y + dy;
        if ((unsigned)yy < 256u) mv = fmaxf(mv, s[yy * 256 + x]);
    }
    vm[b * 65536 + i0] = mv;
}

__device__ __forceinline__ void ins3(float h, int p, float* bv, int* bi)
{
    if (h > bv[0] || (h == bv[0] && p < bi[0])) {
        bv[2]=bv[1]; bi[2]=bi[1]; bv[1]=bv[0]; bi[1]=bi[0]; bv[0]=h; bi[0]=p;
    } else if (h > bv[1] || (h == bv[1] && p < bi[1])) {
        bv[2]=bv[1]; bi[2]=bi[1]; bv[1]=h; bi[1]=p;
    } else if (h > bv[2] || (h == bv[2] && p < bi[2])) {
        bv[2]=h; bi[2]=p;
    }
}
__device__ __forceinline__ void ins2(float h, int p, float* bv, int* bi)
{
    if (h > bv[0] || (h == bv[0] && p < bi[0])) {
        bv[1]=bv[0]; bi[1]=bi[0]; bv[0]=h; bi[0]=p;
    } else if (h > bv[1] || (h == bv[1] && p < bi[1])) {
        bv[1]=h; bi[1]=p;
    }
}

__global__ void k_peaks_part(const float* __restrict__ heat, const float* __restrict__ vm)
{
    int b = blockIdx.y, q = blockIdx.x, tid = threadIdx.x;
    const float* s = heat + b * 65536;
    const float* v = vm   + b * 65536;
    const int pbase = q * 8192;

    float tv[3] = {-INFINITY,-INFINITY,-INFINITY};
    int   ti[3] = {0x7fffffff,0x7fffffff,0x7fffffff};
    float av = -INFINITY; int ai = 0x7fffffff;

    for (int p = pbase + tid; p < pbase + 8192; p += 256) {
        float h = s[p];
        if (h > av) { av = h; ai = p; }
        int y = p >> 8, x = p & 255;
        float mx = -INFINITY;
        #pragma unroll
        for (int dx = -4; dx <= 4; ++dx) {
            int xx = x + dx;
            if ((unsigned)xx < 256u) mx = fmaxf(mx, v[y * 256 + xx]);
        }
        if (h == mx && h > 0.1f) {
            if (h > tv[0]) {
                tv[2]=tv[1]; ti[2]=ti[1]; tv[1]=tv[0]; ti[1]=ti[0]; tv[0]=h; ti[0]=p;
            } else if (h > tv[1]) {
                tv[2]=tv[1]; ti[2]=ti[1]; tv[1]=h; ti[1]=p;
            } else if (h > tv[2]) {
                tv[2]=h; ti[2]=p;
            }
        }
    }

    __shared__ float sv[256*3], sav[256];
    __shared__ int   sj[256*3], sai[256];
    __shared__ float wv[8*3], wav[8];
    __shared__ int   wj[8*3], wai[8];
    #pragma unroll
    for (int k = 0; k < 3; ++k) { sv[tid*3+k] = tv[k]; sj[tid*3+k] = ti[k]; }
    sav[tid] = av; sai[tid] = ai;
    __syncthreads();

    if ((tid & 31) == 0) {
        int w = tid >> 5;
        float bv[3] = {-INFINITY,-INFINITY,-INFINITY};
        int   bi[3] = {0x7fffffff,0x7fffffff,0x7fffffff};
        float bav = -INFINITY; int bai = 0x7fffffff;
        for (int t = tid; t < tid + 32; ++t) {
            #pragma unroll
            for (int k = 0; k < 3; ++k) {
                float h = sv[t*3+k];
                if (h != -INFINITY) ins3(h, sj[t*3+k], bv, bi);
            }
            if (sav[t] > bav || (sav[t] == bav && sai[t] < bai)) { bav = sav[t]; bai = sai[t]; }
        }
        #pragma unroll
        for (int k = 0; k < 3; ++k) { wv[w*3+k] = bv[k]; wj[w*3+k] = bi[k]; }
        wav[w] = bav; wai[w] = bai;
    }
    __syncthreads();

    if (tid == 0) {
        float bv[3] = {-INFINITY,-INFINITY,-INFINITY};
        int   bi[3] = {0x7fffffff,0x7fffffff,0x7fffffff};
        float bav = -INFINITY; int bai = 0x7fffffff;
        for (int w = 0; w < 8; ++w) {
            #pragma unroll
            for (int k = 0; k < 3; ++k) {
                float h = wv[w*3+k];
                if (h != -INFINITY) ins3(h, wj[w*3+k], bv, bi);
            }
            if (wav[w] > bav || (wav[w] == bav && wai[w] < bai)) { bav = wav[w]; bai = wai[w]; }
        }
        int o = (b * PQ + q) * 4;
        #pragma unroll
        for (int k = 0; k < 3; ++k) { g_ppv[o+k] = bv[k]; g_ppi[o+k] = bi[k]; }
        g_ppv[o+3] = bav; g_ppi[o+3] = bai;
    }
}

__global__ void k_pmerge()
{
    int b = threadIdx.x;
    if (b >= 32) return;
    float bv[3] = {-INFINITY,-INFINITY,-INFINITY};
    int   bi[3] = {0x7fffffff,0x7fffffff,0x7fffffff};
    float bav = -INFINITY; int bai = 0x7fffffff;
    for (int q = 0; q < PQ; ++q) {
        int o = (b * PQ + q) * 4;
        #pragma unroll
        for (int k = 0; k < 3; ++k) {
            float h = g_ppv[o+k];
            if (h != -INFINITY) ins3(h, g_ppi[o+k], bv, bi);
        }
        float avv = g_ppv[o+3]; int aii = g_ppi[o+3];
        if (avv > bav || (avv == bav && aii < bai)) { bav = avv; bai = aii; }
    }
    g_pos_idx[b*3+0]   = (bv[0] != -INFINITY) ? bi[0] : bai;
    g_pos_valid[b*3+0] = 1;
    g_pos_idx[b*3+1]   = bi[1];
    g_pos_valid[b*3+1] = (bv[1] != -INFINITY) ? 1 : 0;
    g_pos_idx[b*3+2]   = bi[2];
    g_pos_valid[b*3+2] = (bv[2] != -INFINITY) ? 1 : 0;
}

__device__ __forceinline__ void threefry2x32_dev(unsigned c0, unsigned c1,
                                                 unsigned &o0, unsigned &o1)
{
    const unsigned ks0 = 0u, ks1 = 42u, ks2 = 0x1BD11BDAu ^ 0u ^ 42u;
    unsigned x0 = c0 + ks0, x1 = c1 + ks1;
#define TFR(d) { x0 += x1; x1 = (x1 << d) | (x1 >> (32 - d)); x1 ^= x0; }
    TFR(13) TFR(15) TFR(26) TFR(6)  x0 += ks1; x1 += ks2 + 1u;
    TFR(17) TFR(29) TFR(16) TFR(24) x0 += ks2; x1 += ks0 + 2u;
    TFR(13) TFR(15) TFR(26) TFR(6)  x0 += ks0; x1 += ks1 + 3u;
    TFR(17) TFR(29) TFR(16) TFR(24) x0 += ks1; x1 += ks2 + 4u;
    TFR(13) TFR(15) TFR(26) TFR(6)  x0 += ks2; x1 += ks0 + 5u;
#undef TFR
    o0 = x0; o1 = x1;
}

__global__ void k_neg_part(const float* __restrict__ heat)
{
    int b = blockIdx.y, q = blockIdx.x, tid = threadIdx.x;
    const float* s = heat + b * 65536;
    const int pbase = q * 8192;

    int p0 = g_pos_valid[b*3+0] ? g_pos_idx[b*3+0] : -1;
    int p1 = g_pos_valid[b*3+1] ? g_pos_idx[b*3+1] : -1;
    int p2 = g_pos_valid[b*3+2] ? g_pos_idx[b*3+2] : -1;

    float tv[2] = {-INFINITY,-INFINITY};
    int   ti[2] = {0x7fffffff,0x7fffffff};

    for (int p = pbase + tid; p < pbase + 8192; p += 256) {
        float h = s[p];
        if (h < 0.3f && p != p0 && p != p1 && p != p2) {
            unsigned n = (unsigned)(b * 65536 + p), w0, w1;
            threefry2x32_dev(0u, n, w0, w1);
            unsigned bits = w0 ^ w1;
            float r = __uint_as_float((bits >> 9) | 0x3f800000u) - 1.0f;
            if (r > tv[0]) { tv[1]=tv[0]; ti[1]=ti[0]; tv[0]=r; ti[0]=p; }
            else if (r > tv[1]) { tv[1]=r; ti[1]=p; }
        }
    }

    __shared__ float sv[256*2];
    __shared__ int   sj[256*2];
    __shared__ float wv[8*2];
    __shared__ int   wj[8*2];
    sv[tid*2+0] = tv[0]; sj[tid*2+0] = ti[0];
    sv[tid*2+1] = tv[1]; sj[tid*2+1] = ti[1];
    __syncthreads();

    if ((tid & 31) == 0) {
        int w = tid >> 5;
        float bv[2] = {-INFINITY,-INFINITY};
        int   bi[2] = {0x7fffffff,0x7fffffff};
        for (int t = tid; t < tid + 32; ++t) {
            #pragma unroll
            for (int k = 0; k < 2; ++k) {
                float r = sv[t*2+k];
                if (r != -INFINITY) ins2(r, sj[t*2+k], bv, bi);
            }
        }
        wv[w*2+0] = bv[0]; wj[w*2+0] = bi[0];
        wv[w*2+1] = bv[1]; wj[w*2+1] = bi[1];
    }
    __syncthreads();

    if (tid == 0) {
        float bv[2] = {-INFINITY,-INFINITY};
        int   bi[2] = {0x7fffffff,0x7fffffff};
        for (int w = 0; w < 8; ++w) {
            #pragma unroll
            for (int k = 0; k < 2; ++k) {
                float r = wv[w*2+k];
                if (r != -INFINITY) ins2(r, wj[w*2+k], bv, bi);
            }
        }
        int o = (b * PQ + q) * 2;
        g_npv[o+0] = bv[0]; g_npi[o+0] = bi[0];
        g_npv[o+1] = bv[1]; g_npi[o+1] = bi[1];
    }
}

// merged nmerge + finalize
__global__ void k_nfin(float* __restrict__ coords, float* __restrict__ labels)
{
    int b = threadIdx.x;
    if (b >= 32) return;
    float bv[2] = {-INFINITY,-INFINITY};
    int   bi[2] = {0x7fffffff,0x7fffffff};
    for (int q = 0; q < PQ; ++q) {
        int o = (b * PQ + q) * 2;
        #pragma unroll
        for (int k = 0; k < 2; ++k) {
            float r = g_npv[o+k];
            if (r != -INFINITY) ins2(r, g_npi[o+k], bv, bi);
        }
    }
    int idxs[5], valid[5]; float lab[5];
    #pragma unroll
    for (int k = 0; k < 3; ++k) {
        idxs[k] = g_pos_idx[b*3+k]; valid[k] = g_pos_valid[b*3+k]; lab[k] = 1.f;
    }
    idxs[3] = bi[0]; valid[3] = (bv[0] != -INFINITY) ? 1 : 0; lab[3] = 0.f;
    idxs[4] = bi[1]; valid[4] = (bv[1] != -INFINITY) ? 1 : 0; lab[4] = 0.f;

    float cx[5], cy[5], cl[5];
    #pragma unroll
    for (int s = 0; s < 5; ++s) { cx[s] = 0.f; cy[s] = 0.f; cl[s] = -1.f; }
    int cnt = 0;
    for (int k = 0; k < 5; ++k) {
        if (valid[k]) {
            cx[cnt] = (float)(idxs[k] & 255);
            cy[cnt] = (float)(idxs[k] >> 8);
            cl[cnt] = lab[k];
            ++cnt;
        }
    }
    for (int s = 0; s < 5; ++s) {
        coords[b*10 + s*2 + 0] = cx[s];
        coords[b*10 + s*2 + 1] = cy[s];
        labels[b*5 + s] = cl[s];
    }
}

extern "C" void kernel_launch(void* const* d_in, const int* in_sizes, int n_in,
                              void* d_out, int out_size)
{
    const float* x  = (const float*)d_in[0];
    const float* W1 = (const float*)d_in[1];
    const float* g1 = (const float*)d_in[2];
    const float* b1 = (const float*)d_in[3];
    const float* m1 = (const float*)d_in[4];
    const float* v1 = (const float*)d_in[5];
    const float* W2 = (const float*)d_in[6];
    const float* g2 = (const float*)d_in[7];
    const float* b2 = (const float*)d_in[8];
    const float* m2 = (const float*)d_in[9];
    const float* v2 = (const float*)d_in[10];
    const float* W3 = (const float*)d_in[11];
    const float* b3 = (const float*)d_in[12];

    float* out    = (float*)d_out;
    float* heat   = out;
    float* coords = out + 2097152;
    float* labels = out + 2097472;
    float* logits = out + 2097632;

    float *p_h1, *p_h2, *p_l64, *p_vm, *p_w1r, *p_w2r;
    cudaGetSymbolAddress((void**)&p_h1,  g_h1);
    cudaGetSymbolAddress((void**)&p_h2,  g_h2);
    cudaGetSymbolAddress((void**)&p_l64, g_logits64);
    cudaGetSymbolAddress((void**)&p_vm,  g_vmax);
    cudaGetSymbolAddress((void**)&p_w1r, g_w1r);
    cudaGetSymbolAddress((void**)&p_w2r, g_w2r);

    const int SMEMSZ = 3 * BUF_F * 4;   // 86400 B
    static bool attr_done = false;
    if (!attr_done) {
        cudaFuncSetAttribute(k_conv3x3<256>, cudaFuncAttributeMaxDynamicSharedMemorySize, SMEMSZ);
        cudaFuncSetAttribute(k_conv3x3<64>,  cudaFuncAttributeMaxDynamicSharedMemorySize, SMEMSZ);
        attr_done = true;
    }

    k_reformat<<<576, 256>>>(W1, p_w1r, 256);
    k_reformat<<<144, 256>>>(W2, p_w2r, 64);

    k_conv3x3<256><<<dim3(16, 32), 256, SMEMSZ>>>(x,    p_h1, p_w1r, g1, b1, m1, v1);
    k_conv3x3<64> <<<dim3(16, 32), 256, SMEMSZ>>>(p_h1, p_h2, p_w2r, g2, b2, m2, v2);

    k_conv1x1<<<512, 256>>>(p_h2, W3, b3, p_l64);
    k_resize<<<dim3(256, 32), 256>>>(p_l64, heat, logits);

    k_vmax      <<<dim3(256, 32), 256>>>(heat, p_vm);
    k_peaks_part<<<dim3(PQ, 32), 256>>>(heat, p_vm);
    k_pmerge    <<<1, 32>>>();
    k_neg_part  <<<dim3(PQ, 32), 256>>>(heat);
    k_nfin      <<<1, 32>>>(coords, labels);
}

// round 16
// speedup vs baseline: 1.1086x; 1.0020x over previous
#include <cuda_runtime.h>
#include <cstdint>
#include <math.h>

typedef unsigned long long ull;
struct __align__(16) ULL2 { ull x, y; };

__device__ float g_h1[32*64*64*64];
__device__ float g_h2[32*64*64*64];
__device__ float g_logits64[32*64*64];
__device__ float g_vmax[32*256*256];
__device__ float g_w1r[256*9*64];
__device__ float g_w2r[64*9*64];
__device__ int   g_pos_idx[32*3], g_pos_valid[32*3], g_neg_idx[32*2], g_neg_valid[32*2];
#define PQ 8
__device__ float g_ppv[32*PQ*4]; __device__ int g_ppi[32*PQ*4];
__device__ float g_npv[32*PQ*2]; __device__ int g_npi[32*PQ*2];

__device__ __forceinline__ ull pk2(float lo, float hi)
{ ull r; asm("mov.b64 %0, {%1, %2};" : "=l"(r) : "f"(lo), "f"(hi)); return r; }
__device__ __forceinline__ void upk2(ull v, float& lo, float& hi)
{ asm("mov.b64 {%0, %1}, %2;" : "=f"(lo), "=f"(hi) : "l"(v)); }
__device__ __forceinline__ void fma2(ull& d, ull a, ull b)
{ asm("fma.rn.f32x2 %0, %1, %2, %0;" : "+l"(d) : "l"(a), "l"(b)); }

__device__ __forceinline__ void cp4_zfill(uint32_t d, const void* s, int sz)
{ asm volatile("cp.async.ca.shared.global [%0], [%1], 4, %2;" :: "r"(d), "l"(s), "r"(sz)); }
__device__ __forceinline__ void cp16(uint32_t d, const void* s)
{ asm volatile("cp.async.cg.shared.global [%0], [%1], 16;" :: "r"(d), "l"(s)); }
__device__ __forceinline__ void cp_commit() { asm volatile("cp.async.commit_group;"); }
template<int N> __device__ __forceinline__ void cp_wait()
{ asm volatile("cp.async.wait_group %0;" :: "n"(N) : "memory"); }

__global__ void k_reformat(const float* __restrict__ W, float* __restrict__ out, int cin)
{
    int i = blockIdx.x * blockDim.x + threadIdx.x;
    if (i >= 64 * cin * 9) return;
    int oc = i & 63, rest = i >> 6, tap = rest % 9, ic = rest / 9;
    out[i] = W[(oc * cin + ic) * 9 + tap];
}

// ---- 3x3 conv + BN + ReLU: triple-buffered cp.async, ONE barrier per chunk
// (wait<1> -> sync -> stage(c+2) -> compute(c)); icl loop unrolled x4 so
// ptxas software-pipelines the next channel's LDS ramp into the current
// channel's FMA2 stream. Bit-identical math order.
#define BUF_F 7200            // floats per buffer (2592 input + 4608 weights)
template<int CIN>
__global__ __launch_bounds__(256, 2)
void k_conv3x3(const float* __restrict__ in, float* __restrict__ out,
               const float* __restrict__ wr,
               const float* __restrict__ gg, const float* __restrict__ bb,
               const float* __restrict__ mm, const float* __restrict__ vv)
{
    extern __shared__ float dsm[];      // 3 * BUF_F floats

    const int b    = blockIdx.y;
    const int tile = blockIdx.x;
    const int ty0  = (tile >> 2) * 16;
    const int tx0  = (tile & 3) * 16;
    const int tid  = threadIdx.x;
    const int t_oc = tid >> 5;
    const int t_px = tid & 31;
    const int row  = t_px >> 1;
    const int seg  = (t_px & 1) * 8;

    const uint32_t sb = (uint32_t)__cvta_generic_to_shared(dsm);

    auto stage = [&](int c0, int d) {
        uint32_t in_dst = sb + d * (BUF_F * 4);
        uint32_t w_dst  = in_dst + 2592 * 4;
        #pragma unroll
        for (int k = 0; k < 11; ++k) {
            int i = tid + k * 256;
            if (i < 2592) {
                int icl = i / 324;
                int rem = i - icl * 324;
                int yy  = rem / 18;
                int xx  = rem - yy * 18;
                int gy = ty0 - 1 + yy, gx = tx0 - 1 + xx;
                bool ok = ((unsigned)gy < 64u) & ((unsigned)gx < 64u);
                const float* src = ok ? &in[((b * CIN + c0 + icl) * 64 + gy) * 64 + gx] : in;
                cp4_zfill(in_dst + i * 4, src, ok ? 4 : 0);
            }
        }
        #pragma unroll
        for (int k = 0; k < 5; ++k) {
            int i = tid + k * 256;
            if (i < 1152) cp16(w_dst + i * 16, &wr[c0 * 576 + i * 4]);
        }
        cp_commit();
    };

    ull acc[8][4];
    #pragma unroll
    for (int j = 0; j < 8; ++j)
        #pragma unroll
        for (int k = 0; k < 4; ++k) acc[j][k] = 0ull;

    const int nchunk = CIN / 8;
    stage(0, 0);
    if (nchunk > 1) stage(8, 1);

    int dc = 0;
    for (int c = 0; c < nchunk; ++c) {
        if (c + 1 < nchunk) cp_wait<1>(); else cp_wait<0>();
        __syncthreads();
        if (c + 2 < nchunk) {
            int ds = dc + 2; if (ds >= 3) ds -= 3;
            stage((c + 2) * 8, ds);
        }

        const float* s_in = dsm + dc * BUF_F;
        const float* s_w  = s_in + 2592;
        #pragma unroll 4
        for (int icl = 0; icl < 8; ++icl) {
            const float* si = &s_in[icl * 324 + row * 18 + seg];
            const float* sw = &s_w[icl * 576 + t_oc * 8];
            #pragma unroll
            for (int ty = 0; ty < 3; ++ty) {
                ull rin2[10];
                #pragma unroll
                for (int xx = 0; xx < 10; ++xx) {
                    float v = si[ty * 18 + xx];
                    rin2[xx] = pk2(v, v);
                }
                #pragma unroll
                for (int tx = 0; tx < 3; ++tx) {
                    const int tap = ty * 3 + tx;
                    const ULL2 wA = *(const ULL2*)&sw[tap * 64];
                    const ULL2 wB = *(const ULL2*)&sw[tap * 64 + 4];
                    #pragma unroll
                    for (int j = 0; j < 8; ++j) {
                        ull xp = rin2[j + tx];
                        fma2(acc[j][0], xp, wA.x);
                        fma2(acc[j][1], xp, wA.y);
                        fma2(acc[j][2], xp, wB.x);
                        fma2(acc[j][3], xp, wB.y);
                    }
                }
            }
        }
        if (++dc == 3) dc = 0;
    }

    const int y = ty0 + row, x = tx0 + seg;
    #pragma unroll
    for (int kp = 0; kp < 4; ++kp) {
        int oc0 = t_oc * 8 + 2 * kp, oc1 = oc0 + 1;
        float sc0 = gg[oc0] / sqrtf(vv[oc0] + 1e-5f);
        float sh0 = bb[oc0] - mm[oc0] * sc0;
        float sc1 = gg[oc1] / sqrtf(vv[oc1] + 1e-5f);
        float sh1 = bb[oc1] - mm[oc1] * sc1;
        float a0[8], a1[8];
        #pragma unroll
        for (int j = 0; j < 8; ++j) upk2(acc[j][kp], a0[j], a1[j]);

        float4 o0, o1;
        o0.x = fmaxf(fmaf(a0[0], sc0, sh0), 0.f);
        o0.y = fmaxf(fmaf(a0[1], sc0, sh0), 0.f);
        o0.z = fmaxf(fmaf(a0[2], sc0, sh0), 0.f);
        o0.w = fmaxf(fmaf(a0[3], sc0, sh0), 0.f);
        o1.x = fmaxf(fmaf(a0[4], sc0, sh0), 0.f);
        o1.y = fmaxf(fmaf(a0[5], sc0, sh0), 0.f);
        o1.z = fmaxf(fmaf(a0[6], sc0, sh0), 0.f);
        o1.w = fmaxf(fmaf(a0[7], sc0, sh0), 0.f);
        float* dst0 = &out[((b * 64 + oc0) * 64 + y) * 64 + x];
        *(float4*)dst0 = o0;
        *(float4*)(dst0 + 4) = o1;

        o0.x = fmaxf(fmaf(a1[0], sc1, sh1), 0.f);
        o0.y = fmaxf(fmaf(a1[1], sc1, sh1), 0.f);
        o0.z = fmaxf(fmaf(a1[2], sc1, sh1), 0.f);
        o0.w = fmaxf(fmaf(a1[3], sc1, sh1), 0.f);
        o1.x = fmaxf(fmaf(a1[4], sc1, sh1), 0.f);
        o1.y = fmaxf(fmaf(a1[5], sc1, sh1), 0.f);
        o1.z = fmaxf(fmaf(a1[6], sc1, sh1), 0.f);
        o1.w = fmaxf(fmaf(a1[7], sc1, sh1), 0.f);
        float* dst1 = &out[((b * 64 + oc1) * 64 + y) * 64 + x];
        *(float4*)dst1 = o0;
        *(float4*)(dst1 + 4) = o1;
    }
}

__global__ void k_conv1x1(const float* __restrict__ in, const float* __restrict__ w3,
                          const float* __restrict__ b3, float* __restrict__ out)
{
    int i = blockIdx.x * blockDim.x + threadIdx.x;
    int b = i >> 12, p = i & 4095;
    const float* base = in + (size_t)(b * 64) * 4096 + p;
    float s = 0.f;
    #pragma unroll 8
    for (int ic = 0; ic < 64; ++ic)
        s = fmaf(base[(size_t)ic * 4096], __ldg(&w3[ic]), s);
    out[i] = s + b3[0];
}

__global__ void k_resize(const float* __restrict__ lg,
                         float* __restrict__ heat, float* __restrict__ logits_out)
{
    int ox = threadIdx.x, oy = blockIdx.x, b = blockIdx.y;
    float sy = 0.25f * oy - 0.375f;
    float sx = 0.25f * ox - 0.375f;
    int y0; float fy;
    if (sy <= 0.f)       { y0 = 0;  fy = 0.f; }
    else if (sy >= 63.f) { y0 = 62; fy = 1.f; }
    else                 { y0 = (int)sy; fy = sy - (float)y0; }
    int x0; float fx;
    if (sx <= 0.f)       { x0 = 0;  fx = 0.f; }
    else if (sx >= 63.f) { x0 = 62; fx = 1.f; }
    else                 { x0 = (int)sx; fx = sx - (float)x0; }
    const float* src = lg + b * 4096;
    float v00 = src[y0 * 64 + x0],     v01 = src[y0 * 64 + x0 + 1];
    float v10 = src[(y0+1) * 64 + x0], v11 = src[(y0+1) * 64 + x0 + 1];
    float a = v00 * (1.f - fx) + v01 * fx;
    float c = v10 * (1.f - fx) + v11 * fx;
    float val = a * (1.f - fy) + c * fy;
    int o = b * 65536 + oy * 256 + ox;
    logits_out[o] = val;
    heat[o] = 1.f / (1.f + expf(-val));
}

__global__ void k_vmax(const float* __restrict__ heat, float* __restrict__ vm)
{
    int b = blockIdx.y, i0 = blockIdx.x * blockDim.x + threadIdx.x;
    int y = i0 >> 8, x = i0 & 255;
    const float* s = heat + b * 65536;
    float mv = -INFINITY;
    #pragma unroll
    for (int dy = -4; dy <= 4; ++dy) {
        int yy = y + dy;
        if ((unsigned)yy < 256u) mv = fmaxf(mv, s[yy * 256 + x]);
    }
    vm[b * 65536 + i0] = mv;
}

__device__ __forceinline__ void ins3(float h, int p, float* bv, int* bi)
{
    if (h > bv[0] || (h == bv[0] && p < bi[0])) {
        bv[2]=bv[1]; bi[2]=bi[1]; bv[1]=bv[0]; bi[1]=bi[0]; bv[0]=h; bi[0]=p;
    } else if (h > bv[1] || (h == bv[1] && p < bi[1])) {
        bv[2]=bv[1]; bi[2]=bi[1]; bv[1]=h; bi[1]=p;
    } else if (h > bv[2] || (h == bv[2] && p < bi[2])) {
        bv[2]=h; bi[2]=p;
    }
}
__device__ __forceinline__ void ins2(float h, int p, float* bv, int* bi)
{
    if (h > bv[0] || (h == bv[0] && p < bi[0])) {
        bv[1]=bv[0]; bi[1]=bi[0]; bv[0]=h; bi[0]=p;
    } else if (h > bv[1] || (h == bv[1] && p < bi[1])) {
        bv[1]=h; bi[1]=p;
    }
}

__global__ void k_peaks_part(const float* __restrict__ heat, const float* __restrict__ vm)
{
    int b = blockIdx.y, q = blockIdx.x, tid = threadIdx.x;
    const float* s = heat + b * 65536;
    const float* v = vm   + b * 65536;
    const int pbase = q * 8192;

    float tv[3] = {-INFINITY,-INFINITY,-INFINITY};
    int   ti[3] = {0x7fffffff,0x7fffffff,0x7fffffff};
    float av = -INFINITY; int ai = 0x7fffffff;

    for (int p = pbase + tid; p < pbase + 8192; p += 256) {
        float h = s[p];
        if (h > av) { av = h; ai = p; }
        int y = p >> 8, x = p & 255;
        float mx = -INFINITY;
        #pragma unroll
        for (int dx = -4; dx <= 4; ++dx) {
            int xx = x + dx;
            if ((unsigned)xx < 256u) mx = fmaxf(mx, v[y * 256 + xx]);
        }
        if (h == mx && h > 0.1f) {
            if (h > tv[0]) {
                tv[2]=tv[1]; ti[2]=ti[1]; tv[1]=tv[0]; ti[1]=ti[0]; tv[0]=h; ti[0]=p;
            } else if (h > tv[1]) {
                tv[2]=tv[1]; ti[2]=ti[1]; tv[1]=h; ti[1]=p;
            } else if (h > tv[2]) {
                tv[2]=h; ti[2]=p;
            }
        }
    }

    __shared__ float sv[256*3], sav[256];
    __shared__ int   sj[256*3], sai[256];
    __shared__ float wv[8*3], wav[8];
    __shared__ int   wj[8*3], wai[8];
    #pragma unroll
    for (int k = 0; k < 3; ++k) { sv[tid*3+k] = tv[k]; sj[tid*3+k] = ti[k]; }
    sav[tid] = av; sai[tid] = ai;
    __syncthreads();

    if ((tid & 31) == 0) {
        int w = tid >> 5;
        float bv[3] = {-INFINITY,-INFINITY,-INFINITY};
        int   bi[3] = {0x7fffffff,0x7fffffff,0x7fffffff};
        float bav = -INFINITY; int bai = 0x7fffffff;
        for (int t = tid; t < tid + 32; ++t) {
            #pragma unroll
            for (int k = 0; k < 3; ++k) {
                float h = sv[t*3+k];
                if (h != -INFINITY) ins3(h, sj[t*3+k], bv, bi);
            }
            if (sav[t] > bav || (sav[t] == bav && sai[t] < bai)) { bav = sav[t]; bai = sai[t]; }
        }
        #pragma unroll
        for (int k = 0; k < 3; ++k) { wv[w*3+k] = bv[k]; wj[w*3+k] = bi[k]; }
        wav[w] = bav; wai[w] = bai;
    }
    __syncthreads();

    if (tid == 0) {
        float bv[3] = {-INFINITY,-INFINITY,-INFINITY};
        int   bi[3] = {0x7fffffff,0x7fffffff,0x7fffffff};
        float bav = -INFINITY; int bai = 0x7fffffff;
        for (int w = 0; w < 8; ++w) {
            #pragma unroll
            for (int k = 0; k < 3; ++k) {
                float h = wv[w*3+k];
                if (h != -INFINITY) ins3(h, wj[w*3+k], bv, bi);
            }
            if (wav[w] > bav || (wav[w] == bav && wai[w] < bai)) { bav = wav[w]; bai = wai[w]; }
        }
        int o = (b * PQ + q) * 4;
        #pragma unroll
        for (int k = 0; k < 3; ++k) { g_ppv[o+k] = bv[k]; g_ppi[o+k] = bi[k]; }
        g_ppv[o+3] = bav; g_ppi[o+3] = bai;
    }
}

__global__ void k_pmerge()
{
    int b = threadIdx.x;
    if (b >= 32) return;
    float bv[3] = {-INFINITY,-INFINITY,-INFINITY};
    int   bi[3] = {0x7fffffff,0x7fffffff,0x7fffffff};
    float bav = -INFINITY; int bai = 0x7fffffff;
    for (int q = 0; q < PQ; ++q) {
        int o = (b * PQ + q) * 4;
        #pragma unroll
        for (int k = 0; k < 3; ++k) {
            float h = g_ppv[o+k];
            if (h != -INFINITY) ins3(h, g_ppi[o+k], bv, bi);
        }
        float avv = g_ppv[o+3]; int aii = g_ppi[o+3];
        if (avv > bav || (avv == bav && aii < bai)) { bav = avv; bai = aii; }
    }
    g_pos_idx[b*3+0]   = (bv[0] != -INFINITY) ? bi[0] : bai;
    g_pos_valid[b*3+0] = 1;
    g_pos_idx[b*3+1]   = bi[1];
    g_pos_valid[b*3+1] = (bv[1] != -INFINITY) ? 1 : 0;
    g_pos_idx[b*3+2]   = bi[2];
    g_pos_valid[b*3+2] = (bv[2] != -INFINITY) ? 1 : 0;
}

__device__ __forceinline__ void threefry2x32_dev(unsigned c0, unsigned c1,
                                                 unsigned &o0, unsigned &o1)
{
    const unsigned ks0 = 0u, ks1 = 42u, ks2 = 0x1BD11BDAu ^ 0u ^ 42u;
    unsigned x0 = c0 + ks0, x1 = c1 + ks1;
#define TFR(d) { x0 += x1; x1 = (x1 << d) | (x1 >> (32 - d)); x1 ^= x0; }
    TFR(13) TFR(15) TFR(26) TFR(6)  x0 += ks1; x1 += ks2 + 1u;
    TFR(17) TFR(29) TFR(16) TFR(24) x0 += ks2; x1 += ks0 + 2u;
    TFR(13) TFR(15) TFR(26) TFR(6)  x0 += ks0; x1 += ks1 + 3u;
    TFR(17) TFR(29) TFR(16) TFR(24) x0 += ks1; x1 += ks2 + 4u;
    TFR(13) TFR(15) TFR(26) TFR(6)  x0 += ks2; x1 += ks0 + 5u;
#undef TFR
    o0 = x0; o1 = x1;
}

__global__ void k_neg_part(const float* __restrict__ heat)
{
    int b = blockIdx.y, q = blockIdx.x, tid = threadIdx.x;
    const float* s = heat + b * 65536;
    const int pbase = q * 8192;

    int p0 = g_pos_valid[b*3+0] ? g_pos_idx[b*3+0] : -1;
    int p1 = g_pos_valid[b*3+1] ? g_pos_idx[b*3+1] : -1;
    int p2 = g_pos_valid[b*3+2] ? g_pos_idx[b*3+2] : -1;

    float tv[2] = {-INFINITY,-INFINITY};
    int   ti[2] = {0x7fffffff,0x7fffffff};

    for (int p = pbase + tid; p < pbase + 8192; p += 256) {
        float h = s[p];
        if (h < 0.3f && p != p0 && p != p1 && p != p2) {
            unsigned n = (unsigned)(b * 65536 + p), w0, w1;
            threefry2x32_dev(0u, n, w0, w1);
            unsigned bits = w0 ^ w1;
            float r = __uint_as_float((bits >> 9) | 0x3f800000u) - 1.0f;
            if (r > tv[0]) { tv[1]=tv[0]; ti[1]=ti[0]; tv[0]=r; ti[0]=p; }
            else if (r > tv[1]) { tv[1]=r; ti[1]=p; }
        }
    }

    __shared__ float sv[256*2];
    __shared__ int   sj[256*2];
    __shared__ float wv[8*2];
    __shared__ int   wj[8*2];
    sv[tid*2+0] = tv[0]; sj[tid*2+0] = ti[0];
    sv[tid*2+1] = tv[1]; sj[tid*2+1] = ti[1];
    __syncthreads();

    if ((tid & 31) == 0) {
        int w = tid >> 5;
        float bv[2] = {-INFINITY,-INFINITY};
        int   bi[2] = {0x7fffffff,0x7fffffff};
        for (int t = tid; t < tid + 32; ++t) {
            #pragma unroll
            for (int k = 0; k < 2; ++k) {
                float r = sv[t*2+k];
                if (r != -INFINITY) ins2(r, sj[t*2+k], bv, bi);
            }
        }
        wv[w*2+0] = bv[0]; wj[w*2+0] = bi[0];
        wv[w*2+1] = bv[1]; wj[w*2+1] = bi[1];
    }
    __syncthreads();

    if (tid == 0) {
        float bv[2] = {-INFINITY,-INFINITY};
        int   bi[2] = {0x7fffffff,0x7fffffff};
        for (int w = 0; w < 8; ++w) {
            #pragma unroll
            for (int k = 0; k < 2; ++k) {
                float r = wv[w*2+k];
                if (r != -INFINITY) ins2(r, wj[w*2+k], bv, bi);
            }
        }
        int o = (b * PQ + q) * 2;
        g_npv[o+0] = bv[0]; g_npi[o+0] = bi[0];
        g_npv[o+1] = bv[1]; g_npi[o+1] = bi[1];
    }
}

__global__ void k_nfin(float* __restrict__ coords, float* __restrict__ labels)
{
    int b = threadIdx.x;
    if (b >= 32) return;
    float bv[2] = {-INFINITY,-INFINITY};
    int   bi[2] = {0x7fffffff,0x7fffffff};
    for (int q = 0; q < PQ; ++q) {
        int o = (b * PQ + q) * 2;
        #pragma unroll
        for (int k = 0; k < 2; ++k) {
            float r = g_npv[o+k];
            if (r != -INFINITY) ins2(r, g_npi[o+k], bv, bi);
        }
    }
    int idxs[5], valid[5]; float lab[5];
    #pragma unroll
    for (int k = 0; k < 3; ++k) {
        idxs[k] = g_pos_idx[b*3+k]; valid[k] = g_pos_valid[b*3+k]; lab[k] = 1.f;
    }
    idxs[3] = bi[0]; valid[3] = (bv[0] != -INFINITY) ? 1 : 0; lab[3] = 0.f;
    idxs[4] = bi[1]; valid[4] = (bv[1] != -INFINITY) ? 1 : 0; lab[4] = 0.f;

    float cx[5], cy[5], cl[5];
    #pragma unroll
    for (int s = 0; s < 5; ++s) { cx[s] = 0.f; cy[s] = 0.f; cl[s] = -1.f; }
    int cnt = 0;
    for (int k = 0; k < 5; ++k) {
        if (valid[k]) {
            cx[cnt] = (float)(idxs[k] & 255);
            cy[cnt] = (float)(idxs[k] >> 8);
            cl[cnt] = lab[k];
            ++cnt;
        }
    }
    for (int s = 0; s < 5; ++s) {
        coords[b*10 + s*2 + 0] = cx[s];
        coords[b*10 + s*2 + 1] = cy[s];
        labels[b*5 + s] = cl[s];
    }
}

extern "C" void kernel_launch(void* const* d_in, const int* in_sizes, int n_in,
                              void* d_out, int out_size)
{
    const float* x  = (const float*)d_in[0];
    const float* W1 = (const float*)d_in[1];
    const float* g1 = (const float*)d_in[2];
    const float* b1 = (const float*)d_in[3];
    const float* m1 = (const float*)d_in[4];
    const float* v1 = (const float*)d_in[5];
    const float* W2 = (const float*)d_in[6];
    const float* g2 = (const float*)d_in[7];
    const float* b2 = (const float*)d_in[8];
    const float* m2 = (const float*)d_in[9];
    const float* v2 = (const float*)d_in[10];
    const float* W3 = (const float*)d_in[11];
    const float* b3 = (const float*)d_in[12];

    float* out    = (float*)d_out;
    float* heat   = out;
    float* coords = out + 2097152;
    float* labels = out + 2097472;
    float* logits = out + 2097632;

    float *p_h1, *p_h2, *p_l64, *p_vm, *p_w1r, *p_w2r;
    cudaGetSymbolAddress((void**)&p_h1,  g_h1);
    cudaGetSymbolAddress((void**)&p_h2,  g_h2);
    cudaGetSymbolAddress((void**)&p_l64, g_logits64);
    cudaGetSymbolAddress((void**)&p_vm,  g_vmax);
    cudaGetSymbolAddress((void**)&p_w1r, g_w1r);
    cudaGetSymbolAddress((void**)&p_w2r, g_w2r);

    const int SMEMSZ = 3 * BUF_F * 4;   // 86400 B
    static bool attr_done = false;
    if (!attr_done) {
        cudaFuncSetAttribute(k_conv3x3<256>, cudaFuncAttributeMaxDynamicSharedMemorySize, SMEMSZ);
        cudaFuncSetAttribute(k_conv3x3<64>,  cudaFuncAttributeMaxDynamicSharedMemorySize, SMEMSZ);
        attr_done = true;
    }

    k_reformat<<<576, 256>>>(W1, p_w1r, 256);
    k_reformat<<<144, 256>>>(W2, p_w2r, 64);

    k_conv3x3<256><<<dim3(16, 32), 256, SMEMSZ>>>(x,    p_h1, p_w1r, g1, b1, m1, v1);
    k_conv3x3<64> <<<dim3(16, 32), 256, SMEMSZ>>>(p_h1, p_h2, p_w2r, g2, b2, m2, v2);

    k_conv1x1<<<512, 256>>>(p_h2, W3, b3, p_l64);
    k_resize<<<dim3(256, 32), 256>>>(p_l64, heat, logits);

    k_vmax      <<<dim3(256, 32), 256>>>(heat, p_vm);
    k_peaks_part<<<dim3(PQ, 32), 256>>>(heat, p_vm);
    k_pmerge    <<<1, 32>>>();
    k_neg_part  <<<dim3(PQ, 32), 256>>>(heat);
    k_nfin      <<<1, 32>>>(coords, labels);
}